// round 15
// baseline (speedup 1.0000x reference)
#include <cuda_runtime.h>
#include <cstdint>

#define BB 64
#define TT 512
#define DD 768
#define NC (DD / 4)          // 192 float4 columns
#define NTHR 192
#define ZS 2                 // t-list split factor (blocks per (b,s)) - R2's proven shape
#define MAXN 80
#define KMAX 68              // rel_err ~ 0.985*0.9^69 ~ 7.0e-4 (30% margin under 1e-3)
#define LOG2_DECAY (-0.15200309344504995f)  // log2(0.9)

// scratch (no allocations allowed)
__device__ int   g_ct[2 * BB * MAXN];   // compacted t indices
__device__ float g_cw[2 * BB * MAXN];   // compacted weights
__device__ int   g_cn[2 * BB];          // counts
__device__ float g_ne[2 * BB];          // nonempty flags

__device__ __forceinline__ void fma4(float4& a, float w, const float4& v) {
    a.x += w * v.x; a.y += w * v.y; a.z += w * v.z; a.w += w * v.w;
}

// Kernel A: one block per (b, stream); 512 threads; ballot suffix-scan (proven R5 path).
__global__ void __launch_bounds__(TT) weight_kernel(const float* __restrict__ spk_mask,
                                                    const float* __restrict__ act_mask) {
    int b = blockIdx.x, s = blockIdx.y;
    int t = threadIdx.x, wid = t >> 5, lane = t & 31;
    const float* mask = (s == 0) ? spk_mask : act_mask;

    int m = (mask[b * TT + t] > 0.5f) ? 1 : 0;
    unsigned bal = __ballot_sync(0xFFFFFFFFu, m);

    __shared__ int wcnt[16];
    __shared__ int kcnt[16];
    if (lane == 0) wcnt[wid] = __popc(bal);
    __syncthreads();

    int after = __popc(bal & (0xFFFFFFFEu << lane));
    int total = 0;
    #pragma unroll
    for (int i = 0; i < 16; i++) {
        int c = wcnt[i];
        total += c;
        if (i > wid) after += c;
    }
    int k = after;
    int keep = (m && k <= KMAX) ? 1 : 0;
    float w = keep ? 0.1f * exp2f((float)k * LOG2_DECAY) : 0.0f;

    unsigned kb = __ballot_sync(0xFFFFFFFFu, keep);
    if (lane == 0) kcnt[wid] = __popc(kb);
    __syncthreads();

    int pos = __popc(kb & ((1u << lane) - 1u));
    int n = 0;
    #pragma unroll
    for (int i = 0; i < 16; i++) {
        int c = kcnt[i];
        if (i < wid) pos += c;
        n += c;
    }

    int sb = s * BB + b;
    if (keep) {
        g_ct[sb * MAXN + pos] = t;
        g_cw[sb * MAXN + pos] = w;
    }
    if (t == 0) {
        g_cn[sb] = n;
        g_ne[sb] = (total > 0) ? 1.0f : 0.0f;
    }
}

// Kernel B: grid (BB, 2, ZS), 192 threads. Streams immediately (weights ready),
// REDG epilogue straight into zeroed d_out.
__global__ void __launch_bounds__(NTHR) sum_kernel(
    const float* __restrict__ spk_hist, const float* __restrict__ act_hist,
    const float* __restrict__ spk_mean, const float* __restrict__ act_mean,
    const float* __restrict__ mix_logits, float* __restrict__ out)
{
    const int b = blockIdx.x, s = blockIdx.y, z = blockIdx.z;
    const int sb = s * BB + b;
    const int tid = threadIdx.x;
    const float* X    = (s == 0) ? spk_hist : act_hist;
    const float* mean = (s == 0) ? spk_mean : act_mean;

    __shared__ int   sidx[MAXN];
    __shared__ float swt[MAXN];
    const int n = g_cn[sb];
    if (tid < n) {
        sidx[tid] = g_ct[sb * MAXN + tid];
        swt[tid]  = g_cw[sb * MAXN + tid];
    }
    __syncthreads();

    const float4* base = (const float4*)(X + (size_t)b * TT * DD) + tid;
    float4 acc = make_float4(0.f, 0.f, 0.f, 0.f);

    int j = z;
    // R2's proven loop: 4 independent LDG.128 in flight, stride ZS
    for (; j + 3 * ZS < n; j += 4 * ZS) {
        int   t0 = sidx[j],          t1 = sidx[j + ZS];
        int   t2 = sidx[j + 2 * ZS], t3 = sidx[j + 3 * ZS];
        float w0 = swt[j],           w1 = swt[j + ZS];
        float w2 = swt[j + 2 * ZS],  w3 = swt[j + 3 * ZS];
        float4 v0 = base[(size_t)t0 * NC];
        float4 v1 = base[(size_t)t1 * NC];
        float4 v2 = base[(size_t)t2 * NC];
        float4 v3 = base[(size_t)t3 * NC];
        fma4(acc, w0, v0); fma4(acc, w1, v1); fma4(acc, w2, v2); fma4(acc, w3, v3);
    }
    for (; j < n; j += ZS) {
        float4 v = base[(size_t)sidx[j] * NC];
        fma4(acc, swt[j], v);
    }

    // mean fallback: only z==0 contributes mean when stream empty
    if (g_ne[sb] == 0.0f) {
        if (z == 0) acc = ((const float4*)(mean + (size_t)b * DD))[tid];
        else        acc = make_float4(0.f, 0.f, 0.f, 0.f);
    }

    float l0 = mix_logits[0], l1 = mix_logits[1];
    float mx = fmaxf(l0, l1);
    float e0 = expf(l0 - mx), e1 = expf(l1 - mx);
    float inv = 1.0f / (e0 + e1);
    float w0m = e0 * inv, w1m = e1 * inv;
    float wsel = (s == 0) ? w0m : w1m;

    float* dst_s = out + (size_t)(BB * (1 + s) + b) * DD + tid * 4;  // c_spk / c_act
    float* dst_c = out + (size_t)b * DD + tid * 4;                    // c
    atomicAdd(dst_s + 0, acc.x);
    atomicAdd(dst_s + 1, acc.y);
    atomicAdd(dst_s + 2, acc.z);
    atomicAdd(dst_s + 3, acc.w);
    atomicAdd(dst_c + 0, wsel * acc.x);
    atomicAdd(dst_c + 1, wsel * acc.y);
    atomicAdd(dst_c + 2, wsel * acc.z);
    atomicAdd(dst_c + 3, wsel * acc.w);

    if (b == 0 && s == 0 && z == 0 && tid < 2)
        out[3 * BB * DD + tid] = (tid == 0) ? w0m : w1m;   // w (unique writer)
}

extern "C" void kernel_launch(void* const* d_in, const int* in_sizes, int n_in,
                              void* d_out, int out_size) {
    const float* spk_hist   = (const float*)d_in[0];
    const float* spk_mask   = (const float*)d_in[1];
    const float* act_hist   = (const float*)d_in[2];
    const float* act_mask   = (const float*)d_in[3];
    const float* spk_mean   = (const float*)d_in[4];
    const float* act_mean   = (const float*)d_in[5];
    const float* mix_logits = (const float*)d_in[6];
    float* out = (float*)d_out;

    // zero accumulation targets (graph-capturable async memset, no allocation)
    cudaMemsetAsync(d_out, 0, (size_t)out_size * sizeof(float));

    weight_kernel<<<dim3(BB, 2), TT>>>(spk_mask, act_mask);
    sum_kernel<<<dim3(BB, 2, ZS), NTHR>>>(spk_hist, act_hist,
                                          spk_mean, act_mean, mix_logits, out);
}

// round 16
// speedup vs baseline: 1.1875x; 1.1875x over previous
#include <cuda_runtime.h>
#include <cstdint>

#define BB 64
#define TT 512
#define DD 768
#define NC (DD / 4)
#define NTHR 192
#define ZS 4
#define MAXN 80
#define KMAX 68
#define NKEEP (KMAX + 1)
#define LOG2_DECAY (-0.15200309344504995f)

__device__ __forceinline__ void fma4(float4& a, float w, const float4& v) {
    a.x += w * v.x; a.y += w * v.y; a.z += w * v.z; a.w += w * v.w;
}

__global__ void __launch_bounds__(NTHR) fused_kernel(
    const float* __restrict__ spk_hist, const float* __restrict__ spk_mask,
    const float* __restrict__ act_hist, const float* __restrict__ act_mask,
    const float* __restrict__ spk_mean, const float* __restrict__ act_mean,
    const float* __restrict__ mix_logits, float* __restrict__ out)
{
    const int b = blockIdx.x, s = blockIdx.y, z = blockIdx.z;
    const int tid = threadIdx.x;
    const int wid = tid >> 5, lane = tid & 31;

    const float* mask = (s == 0) ? spk_mask : act_mask;
    const float* X    = (s == 0) ? spk_hist : act_hist;
    const float* mean = (s == 0) ? spk_mean : act_mean;

    __shared__ unsigned bits[16];
    __shared__ int   sidx[MAXN];
    __shared__ float swt[MAXN];

    // Phase 1a: mask -> 512-bit bitmask
    #pragma unroll
    for (int p = 0; p < 3; p++) {
        int t = p * NTHR + tid;
        int m = (t < TT) ? (mask[b * TT + t] > 0.5f ? 1 : 0) : 0;
        unsigned bal = __ballot_sync(0xFFFFFFFFu, m);
        int w = 6 * p + wid;
        if (lane == 0 && w < 16) bits[w] = bal;
    }
    __syncthreads();

    // Phase 1b: redundant in-warp suffix scan; lane i<16 holds suf[i]
    int cw = (lane < 16) ? __popc(bits[lane]) : 0;
    int x = cw;
    #pragma unroll
    for (int off = 1; off < 16; off <<= 1) {
        int y = __shfl_down_sync(0xFFFFFFFFu, x, off);
        if (lane + off < 16) x += y;
    }
    const int total = __shfl_sync(0xFFFFFFFFu, x, 0);
    const int n = (total < NKEEP) ? total : NKEEP;

    // Phase 1c: keep + closed-form position (shfl executed uniformly per p)
    #pragma unroll
    for (int p = 0; p < 3; p++) {
        int w = 6 * p + wid;
        int widx = (w + 1 < 16) ? (w + 1) : 0;         // uniform within warp
        int sufnext = __shfl_sync(0xFFFFFFFFu, x, widx);
        if (w + 1 >= 16) sufnext = 0;
        int t = p * NTHR + tid;
        if (t < TT) {
            unsigned word = bits[w];
            if ((word >> lane) & 1u) {
                int k = sufnext + __popc(word & (0xFFFFFFFEu << lane));
                if (k <= KMAX) {
                    sidx[n - 1 - k] = t;
                    swt[n - 1 - k]  = 0.1f * exp2f((float)k * LOG2_DECAY);
                }
            }
        }
    }
    __syncthreads();

    // Phase 2: weighted sum, 8-wide batches over stride-ZS slice
    const float4* base = (const float4*)(X + (size_t)b * TT * DD) + tid;
    float4 acc = make_float4(0.f, 0.f, 0.f, 0.f);
    int j = z;
    for (; j + 7 * ZS < n; j += 8 * ZS) {
        int   t0 = sidx[j],          t1 = sidx[j + ZS];
        int   t2 = sidx[j + 2 * ZS], t3 = sidx[j + 3 * ZS];
        int   t4 = sidx[j + 4 * ZS], t5 = sidx[j + 5 * ZS];
        int   t6 = sidx[j + 6 * ZS], t7 = sidx[j + 7 * ZS];
        float w0 = swt[j],           w1 = swt[j + ZS];
        float w2 = swt[j + 2 * ZS],  w3 = swt[j + 3 * ZS];
        float w4 = swt[j + 4 * ZS],  w5 = swt[j + 5 * ZS];
        float w6 = swt[j + 6 * ZS],  w7 = swt[j + 7 * ZS];
        float4 v0 = base[(size_t)t0 * NC];
        float4 v1 = base[(size_t)t1 * NC];
        float4 v2 = base[(size_t)t2 * NC];
        float4 v3 = base[(size_t)t3 * NC];
        float4 v4 = base[(size_t)t4 * NC];
        float4 v5 = base[(size_t)t5 * NC];
        float4 v6 = base[(size_t)t6 * NC];
        float4 v7 = base[(size_t)t7 * NC];
        fma4(acc, w0, v0); fma4(acc, w1, v1); fma4(acc, w2, v2); fma4(acc, w3, v3);
        fma4(acc, w4, v4); fma4(acc, w5, v5); fma4(acc, w6, v6); fma4(acc, w7, v7);
    }
    for (; j < n; j += ZS) {
        float4 v = base[(size_t)sidx[j] * NC];
        fma4(acc, swt[j], v);
    }

    // Phase 3: REDG accumulation into zeroed out buffer
    if (total == 0) {
        if (z == 0) acc = ((const float4*)(mean + (size_t)b * DD))[tid];
        else        acc = make_float4(0.f, 0.f, 0.f, 0.f);
    }

    float l0 = mix_logits[0], l1 = mix_logits[1];
    float mx = fmaxf(l0, l1);
    float e0 = expf(l0 - mx), e1 = expf(l1 - mx);
    float inv = 1.0f / (e0 + e1);
    float w0m = e0 * inv, w1m = e1 * inv;
    float wsel = (s == 0) ? w0m : w1m;

    float* dst_s = out + (size_t)(BB * (1 + s) + b) * DD + tid * 4;
    float* dst_c = out + (size_t)b * DD + tid * 4;
    atomicAdd(dst_s + 0, acc.x);
    atomicAdd(dst_s + 1, acc.y);
    atomicAdd(dst_s + 2, acc.z);
    atomicAdd(dst_s + 3, acc.w);
    atomicAdd(dst_c + 0, wsel * acc.x);
    atomicAdd(dst_c + 1, wsel * acc.y);
    atomicAdd(dst_c + 2, wsel * acc.z);
    atomicAdd(dst_c + 3, wsel * acc.w);

    if (b == 0 && s == 0 && z == 0 && tid < 2)
        out[3 * BB * DD + tid] = (tid == 0) ? w0m : w1m;
}

extern "C" void kernel_launch(void* const* d_in, const int* in_sizes, int n_in,
                              void* d_out, int out_size) {
    const float* spk_hist   = (const float*)d_in[0];
    const float* spk_mask   = (const float*)d_in[1];
    const float* act_hist   = (const float*)d_in[2];
    const float* act_mask   = (const float*)d_in[3];
    const float* spk_mean   = (const float*)d_in[4];
    const float* act_mean   = (const float*)d_in[5];
    const float* mix_logits = (const float*)d_in[6];
    float* out = (float*)d_out;

    cudaMemsetAsync(d_out, 0, (size_t)out_size * sizeof(float));

    fused_kernel<<<dim3(BB, 2, ZS), NTHR>>>(spk_hist, spk_mask, act_hist, act_mask,
                                            spk_mean, act_mean, mix_logits, out);
}

// round 17
// speedup vs baseline: 1.1910x; 1.0030x over previous
#include <cuda_runtime.h>
#include <cstdint>

#define BB 64
#define TT 512
#define DD 768
#define NC (DD / 4)
#define NTHR 192
#define ZS 4
#define MAXN 80
#define KMAX 68
#define NKEEP (KMAX + 1)
#define LOG2_DECAY (-0.15200309344504995f)

__device__ __forceinline__ void fma4(float4& a, float w, const float4& v) {
    a.x += w * v.x; a.y += w * v.y; a.z += w * v.z; a.w += w * v.w;
}

// Grid (BB, 2, ZS), 192 threads. Block z owns a CONTIGUOUS chunk of the
// compacted row list (better DRAM locality than stride-ZS interleave).
__global__ void __launch_bounds__(NTHR) fused_kernel(
    const float* __restrict__ spk_hist, const float* __restrict__ spk_mask,
    const float* __restrict__ act_hist, const float* __restrict__ act_mask,
    const float* __restrict__ spk_mean, const float* __restrict__ act_mean,
    const float* __restrict__ mix_logits, float* __restrict__ out)
{
    const int b = blockIdx.x, s = blockIdx.y, z = blockIdx.z;
    const int tid = threadIdx.x;
    const int wid = tid >> 5, lane = tid & 31;

    const float* mask = (s == 0) ? spk_mask : act_mask;
    const float* X    = (s == 0) ? spk_hist : act_hist;
    const float* mean = (s == 0) ? spk_mean : act_mean;

    __shared__ unsigned bits[16];
    __shared__ int   sidx[MAXN];
    __shared__ float swt[MAXN];

    // Phase 1a: mask -> 512-bit bitmask
    #pragma unroll
    for (int p = 0; p < 3; p++) {
        int t = p * NTHR + tid;
        int m = (t < TT) ? (mask[b * TT + t] > 0.5f ? 1 : 0) : 0;
        unsigned bal = __ballot_sync(0xFFFFFFFFu, m);
        int w = 6 * p + wid;
        if (lane == 0 && w < 16) bits[w] = bal;
    }
    __syncthreads();

    // Phase 1b: redundant in-warp suffix scan; lane i<16 holds suf[i]
    int cw = (lane < 16) ? __popc(bits[lane]) : 0;
    int x = cw;
    #pragma unroll
    for (int off = 1; off < 16; off <<= 1) {
        int y = __shfl_down_sync(0xFFFFFFFFu, x, off);
        if (lane + off < 16) x += y;
    }
    const int total = __shfl_sync(0xFFFFFFFFu, x, 0);
    const int n = (total < NKEEP) ? total : NKEEP;

    // Phase 1c: keep + closed-form position pos = n-1-k
    #pragma unroll
    for (int p = 0; p < 3; p++) {
        int w = 6 * p + wid;
        int widx = (w + 1 < 16) ? (w + 1) : 0;         // uniform within warp
        int sufnext = __shfl_sync(0xFFFFFFFFu, x, widx);
        if (w + 1 >= 16) sufnext = 0;
        int t = p * NTHR + tid;
        if (t < TT) {
            unsigned word = bits[w];
            if ((word >> lane) & 1u) {
                int k = sufnext + __popc(word & (0xFFFFFFFEu << lane));
                if (k <= KMAX) {
                    sidx[n - 1 - k] = t;
                    swt[n - 1 - k]  = 0.1f * exp2f((float)k * LOG2_DECAY);
                }
            }
        }
    }
    __syncthreads();

    // Phase 2: weighted sum over CONTIGUOUS chunk [j0, j1)
    const int chunk = (n + ZS - 1) / ZS;
    const int j0 = z * chunk;
    const int j1 = (j0 + chunk < n) ? (j0 + chunk) : n;

    const float4* base = (const float4*)(X + (size_t)b * TT * DD) + tid;
    float4 acc = make_float4(0.f, 0.f, 0.f, 0.f);
    int j = j0;
    for (; j + 8 <= j1; j += 8) {
        int   t0 = sidx[j],     t1 = sidx[j + 1];
        int   t2 = sidx[j + 2], t3 = sidx[j + 3];
        int   t4 = sidx[j + 4], t5 = sidx[j + 5];
        int   t6 = sidx[j + 6], t7 = sidx[j + 7];
        float w0 = swt[j],      w1 = swt[j + 1];
        float w2 = swt[j + 2],  w3 = swt[j + 3];
        float w4 = swt[j + 4],  w5 = swt[j + 5];
        float w6 = swt[j + 6],  w7 = swt[j + 7];
        float4 v0 = base[(size_t)t0 * NC];
        float4 v1 = base[(size_t)t1 * NC];
        float4 v2 = base[(size_t)t2 * NC];
        float4 v3 = base[(size_t)t3 * NC];
        float4 v4 = base[(size_t)t4 * NC];
        float4 v5 = base[(size_t)t5 * NC];
        float4 v6 = base[(size_t)t6 * NC];
        float4 v7 = base[(size_t)t7 * NC];
        fma4(acc, w0, v0); fma4(acc, w1, v1); fma4(acc, w2, v2); fma4(acc, w3, v3);
        fma4(acc, w4, v4); fma4(acc, w5, v5); fma4(acc, w6, v6); fma4(acc, w7, v7);
    }
    for (; j < j1; j++) {
        float4 v = base[(size_t)sidx[j] * NC];
        fma4(acc, swt[j], v);
    }

    // Phase 3: REDG accumulation into zeroed out buffer
    if (total == 0) {
        if (z == 0) acc = ((const float4*)(mean + (size_t)b * DD))[tid];
        else        acc = make_float4(0.f, 0.f, 0.f, 0.f);
    }

    float l0 = mix_logits[0], l1 = mix_logits[1];
    float mx = fmaxf(l0, l1);
    float e0 = expf(l0 - mx), e1 = expf(l1 - mx);
    float inv = 1.0f / (e0 + e1);
    float w0m = e0 * inv, w1m = e1 * inv;
    float wsel = (s == 0) ? w0m : w1m;

    float* dst_s = out + (size_t)(BB * (1 + s) + b) * DD + tid * 4;
    float* dst_c = out + (size_t)b * DD + tid * 4;
    atomicAdd(dst_s + 0, acc.x);
    atomicAdd(dst_s + 1, acc.y);
    atomicAdd(dst_s + 2, acc.z);
    atomicAdd(dst_s + 3, acc.w);
    atomicAdd(dst_c + 0, wsel * acc.x);
    atomicAdd(dst_c + 1, wsel * acc.y);
    atomicAdd(dst_c + 2, wsel * acc.z);
    atomicAdd(dst_c + 3, wsel * acc.w);

    if (b == 0 && s == 0 && z == 0 && tid < 2)
        out[3 * BB * DD + tid] = (tid == 0) ? w0m : w1m;
}

extern "C" void kernel_launch(void* const* d_in, const int* in_sizes, int n_in,
                              void* d_out, int out_size) {
    const float* spk_hist   = (const float*)d_in[0];
    const float* spk_mask   = (const float*)d_in[1];
    const float* act_hist   = (const float*)d_in[2];
    const float* act_mask   = (const float*)d_in[3];
    const float* spk_mean   = (const float*)d_in[4];
    const float* act_mean   = (const float*)d_in[5];
    const float* mix_logits = (const float*)d_in[6];
    float* out = (float*)d_out;

    cudaMemsetAsync(d_out, 0, (size_t)out_size * sizeof(float));

    fused_kernel<<<dim3(BB, 2, ZS), NTHR>>>(spk_hist, spk_mask, act_hist, act_mask,
                                            spk_mean, act_mean, mix_logits, out);
}